// round 2
// baseline (speedup 1.0000x reference)
#include <cuda_runtime.h>
#include <math.h>

#define NN   50000
#define EE   400000
#define GGR  500
#define FIN  92
#define DH   256
#define DEMB 128
#define EPSLN 1e-5f

// ---------------- scratch (no allocations allowed) ----------------
__device__ float g_ha[NN * DH];    // activations
__device__ float g_xw[NN * DH];    // GEMM output (pre-aggregation)
__device__ float g_agg[NN * DH];   // aggregation accumulator
__device__ float g_dinv[NN];       // deg -> rsqrt(deg)
__device__ float g_hg[GGR * DEMB]; // pooled graph embeddings

// ---------------- small helpers ----------------
__device__ __forceinline__ float warp_sum(float v) {
#pragma unroll
    for (int o = 16; o > 0; o >>= 1) v += __shfl_xor_sync(0xffffffffu, v, o);
    return v;
}
__device__ __forceinline__ float lrelu(float v) { return v > 0.f ? v : 0.01f * v; }

// ---------------- degree / norm ----------------
__global__ void k_deg_init() {
    int i = blockIdx.x * blockDim.x + threadIdx.x;
    if (i < NN) g_dinv[i] = 1.0f;  // self-loop contributes 1
}
__global__ void k_deg_count(const int* __restrict__ ei) {
    int e = blockIdx.x * blockDim.x + threadIdx.x;
    if (e < EE) atomicAdd(&g_dinv[ei[EE + e]], 1.0f);  // dst in-degree
}
__global__ void k_deg_finish() {
    int i = blockIdx.x * blockDim.x + threadIdx.x;
    if (i < NN) g_dinv[i] = rsqrtf(g_dinv[i]);
}

// ---------------- SIMT tiled GEMM: C[M,N] = act(A[M,K] @ B[K,N] + bias) ----------------
// 64x64 tile, BK=16, 256 threads, 4x4 per thread.
#define BM 64
#define BN 64
#define BK 16
__global__ __launch_bounds__(256) void k_gemm(
    const float* __restrict__ A, const float* __restrict__ B,
    const float* __restrict__ bias, float* __restrict__ C,
    int M, int K, int N, int act)
{
    __shared__ __align__(16) float As[BK][BM];
    __shared__ __align__(16) float Bs[BK][BN];

    const int bm = blockIdx.y * BM;
    const int bn = blockIdx.x * BN;
    const int tid = threadIdx.x;
    const int tx = tid & 15;   // 16 col-groups
    const int ty = tid >> 4;   // 16 row-groups

    float acc[4][4];
#pragma unroll
    for (int i = 0; i < 4; i++)
#pragma unroll
        for (int j = 0; j < 4; j++) acc[i][j] = 0.f;

    for (int k0 = 0; k0 < K; k0 += BK) {
        // load A tile (64x16) transposed into As[k][m]
#pragma unroll
        for (int i = tid; i < BM * BK; i += 256) {
            int m = i >> 4, kk = i & 15;
            int gr = bm + m, gc = k0 + kk;
            As[kk][m] = (gr < M && gc < K) ? A[(size_t)gr * K + gc] : 0.f;
        }
        // load B tile (16x64)
#pragma unroll
        for (int i = tid; i < BK * BN; i += 256) {
            int kk = i >> 6, n = i & 63;
            int gr = k0 + kk, gc = bn + n;
            Bs[kk][n] = (gr < K && gc < N) ? B[(size_t)gr * N + gc] : 0.f;
        }
        __syncthreads();
#pragma unroll
        for (int kk = 0; kk < BK; kk++) {
            float4 a4 = *(const float4*)&As[kk][ty * 4];
            float4 b4 = *(const float4*)&Bs[kk][tx * 4];
            float a[4] = {a4.x, a4.y, a4.z, a4.w};
            float b[4] = {b4.x, b4.y, b4.z, b4.w};
#pragma unroll
            for (int i = 0; i < 4; i++)
#pragma unroll
                for (int j = 0; j < 4; j++) acc[i][j] = fmaf(a[i], b[j], acc[i][j]);
        }
        __syncthreads();
    }

#pragma unroll
    for (int i = 0; i < 4; i++) {
        int r = bm + ty * 4 + i;
        if (r >= M) continue;
#pragma unroll
        for (int j = 0; j < 4; j++) {
            int c = bn + tx * 4 + j;
            if (c >= N) continue;
            float v = acc[i][j];
            if (bias) v += bias[c];
            if (act) v = lrelu(v);
            C[(size_t)r * N + c] = v;
        }
    }
}

// ---------------- self-loop init: agg = xw * dinv^2 ----------------
template <int D>
__global__ void k_selfloop(const float* __restrict__ xw, float* __restrict__ agg) {
    int idx = blockIdx.x * blockDim.x + threadIdx.x;
    if (idx < NN * D) {
        int i = idx / D;
        float di = g_dinv[i];
        agg[idx] = xw[idx] * di * di;
    }
}

// ---------------- edge scatter: warp per edge ----------------
template <int D>
__global__ __launch_bounds__(256) void k_edge_scatter(
    const int* __restrict__ ei, const float* __restrict__ xw, float* __restrict__ agg)
{
    int w = (blockIdx.x * blockDim.x + threadIdx.x) >> 5;
    int lane = threadIdx.x & 31;
    if (w >= EE) return;
    int s = ei[w];
    int d = ei[EE + w];
    float nrm = g_dinv[s] * g_dinv[d];
    const float4* xs = (const float4*)(xw + (size_t)s * D);
    float* ad = agg + (size_t)d * D;
    constexpr int NV = D / 4;  // float4s per row (64 or 32)
#pragma unroll
    for (int i = lane; i < NV; i += 32) {
        float4 v = xs[i];
        atomicAdd(ad + i * 4 + 0, v.x * nrm);
        atomicAdd(ad + i * 4 + 1, v.y * nrm);
        atomicAdd(ad + i * 4 + 2, v.z * nrm);
        atomicAdd(ad + i * 4 + 3, v.w * nrm);
    }
}

// ---------------- LN epilogue: warp per row ----------------
// out = lrelu( LN(agg + bias) * gam + bet ), optional row L2-normalize.
template <int D, bool L2NORM>
__global__ __launch_bounds__(256) void k_ln(
    const float* __restrict__ agg, const float* __restrict__ bias,
    const float* __restrict__ gam, const float* __restrict__ bet,
    float* __restrict__ out)
{
    int row = (blockIdx.x * blockDim.x + threadIdx.x) >> 5;
    int lane = threadIdx.x & 31;
    if (row >= NN) return;
    constexpr int P = D / 32;
    float v[P];
    const float* a = agg + (size_t)row * D;
    float s = 0.f;
#pragma unroll
    for (int j = 0; j < P; j++) {
        int f = lane + 32 * j;
        v[j] = a[f] + bias[f];
        s += v[j];
    }
    s = warp_sum(s);
    float mu = s * (1.0f / D);
    float q = 0.f;
#pragma unroll
    for (int j = 0; j < P; j++) { float dd = v[j] - mu; q += dd * dd; }
    q = warp_sum(q);
    float r = rsqrtf(q * (1.0f / D) + EPSLN);
    float ss = 0.f;
#pragma unroll
    for (int j = 0; j < P; j++) {
        int f = lane + 32 * j;
        float y = (v[j] - mu) * r * gam[f] + bet[f];
        y = lrelu(y);
        v[j] = y;
        ss += y * y;
    }
    if (L2NORM) {
        ss = warp_sum(ss);
        float inv = 1.0f / fmaxf(sqrtf(ss), 1e-12f);
#pragma unroll
        for (int j = 0; j < P; j++) v[j] *= inv;
    }
    float* o = out + (size_t)row * D;
#pragma unroll
    for (int j = 0; j < P; j++) o[lane + 32 * j] = v[j];
}

// ---------------- global add pool ----------------
__global__ void k_hg_zero() {
    int i = blockIdx.x * blockDim.x + threadIdx.x;
    if (i < GGR * DEMB) g_hg[i] = 0.f;
}
__global__ __launch_bounds__(256) void k_pool(const float* __restrict__ ha,
                                              const int* __restrict__ batch)
{
    int w = (blockIdx.x * blockDim.x + threadIdx.x) >> 5;
    int lane = threadIdx.x & 31;
    if (w >= NN) return;
    int b = batch[w];
    float4 v = ((const float4*)(ha + (size_t)w * DEMB))[lane];
    float* h = g_hg + (size_t)b * DEMB + lane * 4;
    atomicAdd(h + 0, v.x);
    atomicAdd(h + 1, v.y);
    atomicAdd(h + 2, v.z);
    atomicAdd(h + 3, v.w);
}

// ---------------- final MLP: one block (64 thr) per graph ----------------
__global__ __launch_bounds__(64) void k_mlp(
    const float* __restrict__ W1, const float* __restrict__ b1,
    const float* __restrict__ W2, const float* __restrict__ b2,
    float* __restrict__ out)
{
    int g = blockIdx.x;
    int t = threadIdx.x;  // 0..63
    __shared__ float sh[DEMB];
    __shared__ float red[2];
    sh[t] = g_hg[(size_t)g * DEMB + t];
    sh[t + 64] = g_hg[(size_t)g * DEMB + 64 + t];
    __syncthreads();
    float s = b1[t];
#pragma unroll
    for (int k = 0; k < DEMB; k++) s = fmaf(sh[k], W1[k * 64 + t], s);
    s = lrelu(s);
    s *= W2[t];  // fc2_W is [64,1]
    s = warp_sum(s);
    if ((t & 31) == 0) red[t >> 5] = s;
    __syncthreads();
    if (t == 0) out[g] = red[0] + red[1] + b2[0];
}

// ---------------- launch ----------------
extern "C" void kernel_launch(void* const* d_in, const int* in_sizes, int n_in,
                              void* d_out, int out_size)
{
    const float* x     = (const float*)d_in[0];
    const int*   ei    = (const int*)  d_in[1];
    const int*   batch = (const int*)  d_in[2];
    const float* nfcW  = (const float*)d_in[3];
    const float* nfcb  = (const float*)d_in[4];
    const float* gn1g  = (const float*)d_in[5];
    const float* gn1b  = (const float*)d_in[6];
    const float* gc1W  = (const float*)d_in[7];
    const float* gc1b  = (const float*)d_in[8];
    const float* gn2g  = (const float*)d_in[9];
    const float* gn2b  = (const float*)d_in[10];
    const float* gc2W  = (const float*)d_in[11];
    const float* gc2b  = (const float*)d_in[12];
    const float* fc1W  = (const float*)d_in[13];
    const float* fc1b  = (const float*)d_in[14];
    const float* fc2W  = (const float*)d_in[15];
    const float* fc2b  = (const float*)d_in[16];

    float* out   = (float*)d_out;         // [500]
    float* outHa = out + GGR;             // [50000*128]

    float* ha;  cudaGetSymbolAddress((void**)&ha,  g_ha);
    float* xw;  cudaGetSymbolAddress((void**)&xw,  g_xw);
    float* agg; cudaGetSymbolAddress((void**)&agg, g_agg);

    // 1) degree -> dinv
    k_deg_init<<<(NN + 255) / 256, 256>>>();
    k_deg_count<<<(EE + 255) / 256, 256>>>(ei);
    k_deg_finish<<<(NN + 255) / 256, 256>>>();

    // 2) node feature encoder: ha = lrelu(x @ nfc_W + nfc_b)
    {
        dim3 grid(DH / BN, (NN + BM - 1) / BM);
        k_gemm<<<grid, 256>>>(x, nfcW, nfcb, ha, NN, FIN, DH, 1);
    }

    // 3) GCN conv 1: xw = ha @ gc1_W ; aggregate ; +bias, LN, lrelu -> ha
    {
        dim3 grid(DH / BN, (NN + BM - 1) / BM);
        k_gemm<<<grid, 256>>>(ha, gc1W, nullptr, xw, NN, DH, DH, 0);
    }
    k_selfloop<DH><<<(NN * DH + 255) / 256, 256>>>(xw, agg);
    k_edge_scatter<DH><<<(EE * 32 + 255) / 256, 256>>>(ei, xw, agg);
    k_ln<DH, false><<<(NN * 32 + 255) / 256, 256>>>(agg, gc1b, gn1g, gn1b, ha);

    // 4) GCN conv 2: xw = ha @ gc2_W ; aggregate ; +bias, LN, lrelu, L2norm -> outHa
    {
        dim3 grid(DEMB / BN, (NN + BM - 1) / BM);
        k_gemm<<<grid, 256>>>(ha, gc2W, nullptr, xw, NN, DH, DEMB, 0);
    }
    k_selfloop<DEMB><<<(NN * DEMB + 255) / 256, 256>>>(xw, agg);
    k_edge_scatter<DEMB><<<(EE * 32 + 255) / 256, 256>>>(ei, xw, agg);
    k_ln<DEMB, true><<<(NN * 32 + 255) / 256, 256>>>(agg, gc2b, gn2g, gn2b, outHa);

    // 5) global add pool over batch
    k_hg_zero<<<(GGR * DEMB + 255) / 256, 256>>>();
    k_pool<<<(NN * 32 + 255) / 256, 256>>>(outHa, batch);

    // 6) MLP head -> out[500]
    k_mlp<<<GGR, 64>>>(fc1W, fc1b, fc2W, fc2b, out);
}

// round 3
// speedup vs baseline: 1.8097x; 1.8097x over previous
#include <cuda_runtime.h>
#include <math.h>

#define NN   50000
#define EE   400000
#define GGR  500
#define FIN  92
#define DH   256
#define DEMB 128
#define EPSLN 1e-5f

// ---------------- scratch (no allocations allowed) ----------------
__device__ float g_ha[NN * DH];    // activations
__device__ float g_xw[NN * DH];    // GEMM output (pre-aggregation)
__device__ float g_agg[NN * DH];   // aggregation accumulator
__device__ float g_dinv[NN];       // deg -> rsqrt(deg)
__device__ float g_hg[GGR * DEMB]; // pooled graph embeddings

// ---------------- small helpers ----------------
__device__ __forceinline__ float warp_sum(float v) {
#pragma unroll
    for (int o = 16; o > 0; o >>= 1) v += __shfl_xor_sync(0xffffffffu, v, o);
    return v;
}
__device__ __forceinline__ float lrelu(float v) { return v > 0.f ? v : 0.01f * v; }

__device__ __forceinline__ void red_add_v4(float* p, float4 v) {
#if __CUDA_ARCH__ >= 900
    asm volatile("red.global.add.v4.f32 [%0], {%1, %2, %3, %4};"
                 :: "l"(p), "f"(v.x), "f"(v.y), "f"(v.z), "f"(v.w) : "memory");
#else
    atomicAdd(p + 0, v.x);
    atomicAdd(p + 1, v.y);
    atomicAdd(p + 2, v.z);
    atomicAdd(p + 3, v.w);
#endif
}

// ---------------- degree / norm ----------------
__global__ void k_deg_init() {
    int i = blockIdx.x * blockDim.x + threadIdx.x;
    if (i < NN) g_dinv[i] = 1.0f;  // self-loop contributes 1
}
__global__ void k_deg_count(const int* __restrict__ ei) {
    int e = blockIdx.x * blockDim.x + threadIdx.x;
    if (e < EE) atomicAdd(&g_dinv[ei[EE + e]], 1.0f);  // dst in-degree
}
__global__ void k_deg_finish() {
    int i = blockIdx.x * blockDim.x + threadIdx.x;
    if (i < NN) g_dinv[i] = rsqrtf(g_dinv[i]);
}

// ---------------- SIMT tiled GEMM: C[M,N] = act(A[M,K] @ B[K,N] + bias) ----------------
// 128x128 tile, BK=16, 256 threads, 8x8 per thread. 16 FMA per LDS.128.
#define BM 128
#define BN 128
#define BK 16
#define PAD 4
__global__ __launch_bounds__(256) void k_gemm(
    const float* __restrict__ A, const float* __restrict__ B,
    const float* __restrict__ bias, float* __restrict__ C,
    int M, int K, int N, int act)
{
    __shared__ __align__(16) float As[BK][BM + PAD];  // transposed: As[k][m]
    __shared__ __align__(16) float Bs[BK][BN + PAD];

    const int bm = blockIdx.y * BM;
    const int bn = blockIdx.x * BN;
    const int tid = threadIdx.x;
    const int tx = tid & 15;   // 16 col-groups of 8
    const int ty = tid >> 4;   // 16 row-groups of 8

    float acc[8][8];
#pragma unroll
    for (int i = 0; i < 8; i++)
#pragma unroll
        for (int j = 0; j < 8; j++) acc[i][j] = 0.f;

    // A-load mapping: 128 rows x 4 float4-cols = 512 float4s, 2 per thread
    const int a_r0 = tid >> 2;          // 0..63
    const int a_c4 = tid & 3;           // float4 index within BK
    // B-load mapping: 16 rows x 32 float4-cols = 512 float4s, 2 per thread
    const int b_r0 = tid >> 5;          // 0..7
    const int b_c4 = tid & 31;

    for (int k0 = 0; k0 < K; k0 += BK) {
        // load A tile (128x16) transposed into As[k][m], zero-fill OOB
#pragma unroll
        for (int i = 0; i < 2; i++) {
            int r = a_r0 + i * 64;
            int gr = bm + r;
            int gc = k0 + a_c4 * 4;
            float4 v = make_float4(0.f, 0.f, 0.f, 0.f);
            if (gr < M && gc < K)  // K % 4 == 0 for all our shapes
                v = *(const float4*)(A + (size_t)gr * K + gc);
            As[a_c4 * 4 + 0][r] = v.x;
            As[a_c4 * 4 + 1][r] = v.y;
            As[a_c4 * 4 + 2][r] = v.z;
            As[a_c4 * 4 + 3][r] = v.w;
        }
        // load B tile (16x128), zero-fill OOB rows
#pragma unroll
        for (int i = 0; i < 2; i++) {
            int r = b_r0 + i * 8;
            int gr = k0 + r;
            float4 v = make_float4(0.f, 0.f, 0.f, 0.f);
            if (gr < K)
                v = *(const float4*)(B + (size_t)gr * N + bn + b_c4 * 4);
            *(float4*)&Bs[r][b_c4 * 4] = v;
        }
        __syncthreads();

#pragma unroll
        for (int kk = 0; kk < BK; kk++) {
            float a[8], b[8];
            float4 a0 = *(const float4*)&As[kk][ty * 8];
            float4 a1 = *(const float4*)&As[kk][ty * 8 + 4];
            float4 b0 = *(const float4*)&Bs[kk][tx * 8];
            float4 b1 = *(const float4*)&Bs[kk][tx * 8 + 4];
            a[0] = a0.x; a[1] = a0.y; a[2] = a0.z; a[3] = a0.w;
            a[4] = a1.x; a[5] = a1.y; a[6] = a1.z; a[7] = a1.w;
            b[0] = b0.x; b[1] = b0.y; b[2] = b0.z; b[3] = b0.w;
            b[4] = b1.x; b[5] = b1.y; b[6] = b1.z; b[7] = b1.w;
#pragma unroll
            for (int i = 0; i < 8; i++)
#pragma unroll
                for (int j = 0; j < 8; j++) acc[i][j] = fmaf(a[i], b[j], acc[i][j]);
        }
        __syncthreads();
    }

#pragma unroll
    for (int i = 0; i < 8; i++) {
        int r = bm + ty * 8 + i;
        if (r >= M) continue;
        float* crow = C + (size_t)r * N + bn + tx * 8;
#pragma unroll
        for (int j = 0; j < 8; j += 4) {
            float4 v;
            v.x = acc[i][j + 0]; v.y = acc[i][j + 1];
            v.z = acc[i][j + 2]; v.w = acc[i][j + 3];
            if (bias) {
                const float* bb = bias + bn + tx * 8 + j;
                v.x += bb[0]; v.y += bb[1]; v.z += bb[2]; v.w += bb[3];
            }
            if (act) {
                v.x = lrelu(v.x); v.y = lrelu(v.y);
                v.z = lrelu(v.z); v.w = lrelu(v.w);
            }
            *(float4*)(crow + j) = v;
        }
    }
}

// ---------------- self-loop init: agg = xw * dinv^2 ----------------
template <int D>
__global__ void k_selfloop(const float* __restrict__ xw, float* __restrict__ agg) {
    int idx = blockIdx.x * blockDim.x + threadIdx.x;  // float4 index
    if (idx < NN * D / 4) {
        int i = idx / (D / 4);
        float di = g_dinv[i];
        float s = di * di;
        float4 v = ((const float4*)xw)[idx];
        v.x *= s; v.y *= s; v.z *= s; v.w *= s;
        ((float4*)agg)[idx] = v;
    }
}

// ---------------- edge scatter: warp per edge, vector reductions ----------------
template <int D>
__global__ __launch_bounds__(256) void k_edge_scatter(
    const int* __restrict__ ei, const float* __restrict__ xw, float* __restrict__ agg)
{
    int w = (blockIdx.x * blockDim.x + threadIdx.x) >> 5;
    int lane = threadIdx.x & 31;
    if (w >= EE) return;
    int s = ei[w];
    int d = ei[EE + w];
    float nrm = g_dinv[s] * g_dinv[d];
    const float4* xs = (const float4*)(xw + (size_t)s * D);
    float* ad = agg + (size_t)d * D;
    constexpr int NV = D / 4;  // float4s per row (64 or 32)
#pragma unroll
    for (int i = lane; i < NV; i += 32) {
        float4 v = xs[i];
        v.x *= nrm; v.y *= nrm; v.z *= nrm; v.w *= nrm;
        red_add_v4(ad + i * 4, v);
    }
}

// ---------------- LN epilogue: warp per row ----------------
template <int D, bool L2NORM>
__global__ __launch_bounds__(256) void k_ln(
    const float* __restrict__ agg, const float* __restrict__ bias,
    const float* __restrict__ gam, const float* __restrict__ bet,
    float* __restrict__ out)
{
    int row = (blockIdx.x * blockDim.x + threadIdx.x) >> 5;
    int lane = threadIdx.x & 31;
    if (row >= NN) return;
    constexpr int P = D / 32;
    float v[P];
    const float* a = agg + (size_t)row * D;
    float s = 0.f;
#pragma unroll
    for (int j = 0; j < P; j++) {
        int f = lane + 32 * j;
        v[j] = a[f] + bias[f];
        s += v[j];
    }
    s = warp_sum(s);
    float mu = s * (1.0f / D);
    float q = 0.f;
#pragma unroll
    for (int j = 0; j < P; j++) { float dd = v[j] - mu; q += dd * dd; }
    q = warp_sum(q);
    float r = rsqrtf(q * (1.0f / D) + EPSLN);
    float ss = 0.f;
#pragma unroll
    for (int j = 0; j < P; j++) {
        int f = lane + 32 * j;
        float y = (v[j] - mu) * r * gam[f] + bet[f];
        y = lrelu(y);
        v[j] = y;
        ss += y * y;
    }
    if (L2NORM) {
        ss = warp_sum(ss);
        float inv = 1.0f / fmaxf(sqrtf(ss), 1e-12f);
#pragma unroll
        for (int j = 0; j < P; j++) v[j] *= inv;
    }
    float* o = out + (size_t)row * D;
#pragma unroll
    for (int j = 0; j < P; j++) o[lane + 32 * j] = v[j];
}

// ---------------- global add pool ----------------
__global__ void k_hg_zero() {
    int i = blockIdx.x * blockDim.x + threadIdx.x;
    if (i < GGR * DEMB) g_hg[i] = 0.f;
}
__global__ __launch_bounds__(256) void k_pool(const float* __restrict__ ha,
                                              const int* __restrict__ batch)
{
    int w = (blockIdx.x * blockDim.x + threadIdx.x) >> 5;
    int lane = threadIdx.x & 31;
    if (w >= NN) return;
    int b = batch[w];
    float4 v = ((const float4*)(ha + (size_t)w * DEMB))[lane];
    red_add_v4(g_hg + (size_t)b * DEMB + lane * 4, v);
}

// ---------------- final MLP: one block (64 thr) per graph ----------------
__global__ __launch_bounds__(64) void k_mlp(
    const float* __restrict__ W1, const float* __restrict__ b1,
    const float* __restrict__ W2, const float* __restrict__ b2,
    float* __restrict__ out)
{
    int g = blockIdx.x;
    int t = threadIdx.x;  // 0..63
    __shared__ float sh[DEMB];
    __shared__ float red[2];
    sh[t] = g_hg[(size_t)g * DEMB + t];
    sh[t + 64] = g_hg[(size_t)g * DEMB + 64 + t];
    __syncthreads();
    float s = b1[t];
#pragma unroll
    for (int k = 0; k < DEMB; k++) s = fmaf(sh[k], W1[k * 64 + t], s);
    s = lrelu(s);
    s *= W2[t];  // fc2_W is [64,1]
    s = warp_sum(s);
    if ((t & 31) == 0) red[t >> 5] = s;
    __syncthreads();
    if (t == 0) out[g] = red[0] + red[1] + b2[0];
}

// ---------------- launch ----------------
extern "C" void kernel_launch(void* const* d_in, const int* in_sizes, int n_in,
                              void* d_out, int out_size)
{
    const float* x     = (const float*)d_in[0];
    const int*   ei    = (const int*)  d_in[1];
    const int*   batch = (const int*)  d_in[2];
    const float* nfcW  = (const float*)d_in[3];
    const float* nfcb  = (const float*)d_in[4];
    const float* gn1g  = (const float*)d_in[5];
    const float* gn1b  = (const float*)d_in[6];
    const float* gc1W  = (const float*)d_in[7];
    const float* gc1b  = (const float*)d_in[8];
    const float* gn2g  = (const float*)d_in[9];
    const float* gn2b  = (const float*)d_in[10];
    const float* gc2W  = (const float*)d_in[11];
    const float* gc2b  = (const float*)d_in[12];
    const float* fc1W  = (const float*)d_in[13];
    const float* fc1b  = (const float*)d_in[14];
    const float* fc2W  = (const float*)d_in[15];
    const float* fc2b  = (const float*)d_in[16];

    float* out   = (float*)d_out;         // [500]
    float* outHa = out + GGR;             // [50000*128]

    float* ha;  cudaGetSymbolAddress((void**)&ha,  g_ha);
    float* xw;  cudaGetSymbolAddress((void**)&xw,  g_xw);
    float* agg; cudaGetSymbolAddress((void**)&agg, g_agg);

    // 1) degree -> dinv
    k_deg_init<<<(NN + 255) / 256, 256>>>();
    k_deg_count<<<(EE + 255) / 256, 256>>>(ei);
    k_deg_finish<<<(NN + 255) / 256, 256>>>();

    const int MB = (NN + BM - 1) / BM;  // 391

    // 2) node feature encoder: ha = lrelu(x @ nfc_W + nfc_b)
    k_gemm<<<dim3(DH / BN, MB), 256>>>(x, nfcW, nfcb, ha, NN, FIN, DH, 1);

    // 3) GCN conv 1: xw = ha @ gc1_W ; aggregate ; +bias, LN, lrelu -> ha
    k_gemm<<<dim3(DH / BN, MB), 256>>>(ha, gc1W, nullptr, xw, NN, DH, DH, 0);
    k_selfloop<DH><<<(NN * DH / 4 + 255) / 256, 256>>>(xw, agg);
    k_edge_scatter<DH><<<(EE * 32 + 255) / 256, 256>>>(ei, xw, agg);
    k_ln<DH, false><<<(NN * 32 + 255) / 256, 256>>>(agg, gc1b, gn1g, gn1b, ha);

    // 4) GCN conv 2: xw = ha @ gc2_W ; aggregate ; +bias, LN, lrelu, L2norm -> outHa
    k_gemm<<<dim3(DEMB / BN, MB), 256>>>(ha, gc2W, nullptr, xw, NN, DH, DEMB, 0);
    k_selfloop<DEMB><<<(NN * DEMB / 4 + 255) / 256, 256>>>(xw, agg);
    k_edge_scatter<DEMB><<<(EE * 32 + 255) / 256, 256>>>(ei, xw, agg);
    k_ln<DEMB, true><<<(NN * 32 + 255) / 256, 256>>>(agg, gc2b, gn2g, gn2b, outHa);

    // 5) global add pool over batch
    k_hg_zero<<<(GGR * DEMB + 255) / 256, 256>>>();
    k_pool<<<(NN * 32 + 255) / 256, 256>>>(outHa, batch);

    // 6) MLP head -> out[500]
    k_mlp<<<GGR, 64>>>(fc1W, fc1b, fc2W, fc2b, out);
}

// round 5
// speedup vs baseline: 2.3431x; 1.2947x over previous
#include <cuda_runtime.h>
#include <math.h>

#define NN   50000
#define EE   400000
#define GGR  500
#define FIN  92
#define DH   256
#define DEMB 128
#define EPSLN 1e-5f

// ---------------- scratch (no allocations allowed) ----------------
__device__ float g_ha[NN * DH];    // activations
__device__ float g_xw[NN * DH];    // GEMM output (pre-aggregation)
__device__ float g_dinv[NN];       // rsqrt(deg+1)
__device__ int   g_deg[NN];        // in-degree (excl self loop)
__device__ int   g_off[NN];        // CSR offsets (exclusive scan of deg)
__device__ int   g_cur[NN];        // fill cursors
__device__ int   g_csr[EE];        // src node ids grouped by dst
__device__ int   g_bsum[256];      // block sums for scan
__device__ float g_hg[GGR * DEMB]; // pooled graph embeddings

// ---------------- small helpers ----------------
__device__ __forceinline__ float warp_sum(float v) {
#pragma unroll
    for (int o = 16; o > 0; o >>= 1) v += __shfl_xor_sync(0xffffffffu, v, o);
    return v;
}
__device__ __forceinline__ float lrelu(float v) { return v > 0.f ? v : 0.01f * v; }

__device__ __forceinline__ void red_add_v4(float* p, float4 v) {
    asm volatile("red.global.add.v4.f32 [%0], {%1, %2, %3, %4};"
                 :: "l"(p), "f"(v.x), "f"(v.y), "f"(v.z), "f"(v.w) : "memory");
}

// packed f32x2 helpers
__device__ __forceinline__ unsigned long long pack2(float lo, float hi) {
    unsigned long long r;
    asm("mov.b64 %0, {%1, %2};" : "=l"(r)
        : "r"(__float_as_uint(lo)), "r"(__float_as_uint(hi)));
    return r;
}
__device__ __forceinline__ void unpack2(unsigned long long p, float& lo, float& hi) {
    unsigned int a, b;
    asm("mov.b64 {%0, %1}, %2;" : "=r"(a), "=r"(b) : "l"(p));
    lo = __uint_as_float(a); hi = __uint_as_float(b);
}
__device__ __forceinline__ void fma2(unsigned long long& d, unsigned long long a,
                                     unsigned long long b) {
    asm("fma.rn.f32x2 %0, %1, %2, %0;" : "+l"(d) : "l"(a), "l"(b));
}

// ---------------- degree / zero ----------------
__global__ void k_zero() {
    int i = blockIdx.x * blockDim.x + threadIdx.x;
    if (i < NN) g_deg[i] = 0;
    if (i < GGR * DEMB) g_hg[i] = 0.f;
}
__global__ void k_deg_count(const int* __restrict__ ei) {
    int e = blockIdx.x * blockDim.x + threadIdx.x;
    if (e < EE) atomicAdd(&g_deg[ei[EE + e]], 1);
}
__global__ void k_dinv() {
    int i = blockIdx.x * blockDim.x + threadIdx.x;
    if (i < NN) g_dinv[i] = rsqrtf((float)g_deg[i] + 1.0f);
}

// ---------------- exclusive scan of g_deg -> g_off ----------------
__global__ __launch_bounds__(256) void k_scan1() {
    __shared__ int ws[8];
    int i = blockIdx.x * 256 + threadIdx.x;
    int lane = threadIdx.x & 31, w = threadIdx.x >> 5;
    int v = (i < NN) ? g_deg[i] : 0;
    int x = v;
#pragma unroll
    for (int o = 1; o < 32; o <<= 1) {
        int t = __shfl_up_sync(0xffffffffu, x, o);
        if (lane >= o) x += t;
    }
    if (lane == 31) ws[w] = x;
    __syncthreads();
    if (w == 0 && lane < 8) {
        int y = ws[lane];
#pragma unroll
        for (int o = 1; o < 8; o <<= 1) {
            int t = __shfl_up_sync(0xffu, y, o);
            if (lane >= o) y += t;
        }
        ws[lane] = y;
    }
    __syncthreads();
    int base = (w > 0) ? ws[w - 1] : 0;
    if (i < NN) g_off[i] = base + x - v;
    if (threadIdx.x == 255) g_bsum[blockIdx.x] = ws[7];
}
__global__ __launch_bounds__(256) void k_scan2(int nblk) {
    __shared__ int ws[8];
    int lane = threadIdx.x & 31, w = threadIdx.x >> 5;
    int v = (threadIdx.x < nblk) ? g_bsum[threadIdx.x] : 0;
    int x = v;
#pragma unroll
    for (int o = 1; o < 32; o <<= 1) {
        int t = __shfl_up_sync(0xffffffffu, x, o);
        if (lane >= o) x += t;
    }
    if (lane == 31) ws[w] = x;
    __syncthreads();
    if (w == 0 && lane < 8) {
        int y = ws[lane];
#pragma unroll
        for (int o = 1; o < 8; o <<= 1) {
            int t = __shfl_up_sync(0xffu, y, o);
            if (lane >= o) y += t;
        }
        ws[lane] = y;
    }
    __syncthreads();
    int base = (w > 0) ? ws[w - 1] : 0;
    if (threadIdx.x < nblk) g_bsum[threadIdx.x] = base + x - v;
}
__global__ void k_scan3() {
    int i = blockIdx.x * blockDim.x + threadIdx.x;
    if (i < NN) {
        int o = g_off[i] + g_bsum[i >> 8];
        g_off[i] = o;
        g_cur[i] = o;
    }
}
__global__ void k_fill(const int* __restrict__ ei) {
    int e = blockIdx.x * blockDim.x + threadIdx.x;
    if (e < EE) {
        int s = ei[e], d = ei[EE + e];
        int pos = atomicAdd(&g_cur[d], 1);
        g_csr[pos] = s;
    }
}

// ---------------- SIMT tiled GEMM with packed f32x2 FMA ----------------
// 128x128 tile, BK=16, 256 threads, 8x8 per thread (as 8x4 f32x2).
#define BM 128
#define BN 128
#define BK 16
#define PAD 4
__global__ __launch_bounds__(256) void k_gemm(
    const float* __restrict__ A, const float* __restrict__ B,
    const float* __restrict__ bias, float* __restrict__ C,
    int M, int K, int N, int act)
{
    __shared__ __align__(16) float As[BK][BM + PAD];  // transposed: As[k][m]
    __shared__ __align__(16) float Bs[BK][BN + PAD];

    const int bm = blockIdx.y * BM;
    const int bn = blockIdx.x * BN;
    const int tid = threadIdx.x;
    const int tx = tid & 15;   // 16 col-groups of 8
    const int ty = tid >> 4;   // 16 row-groups of 8

    unsigned long long acc[8][4];
#pragma unroll
    for (int i = 0; i < 8; i++)
#pragma unroll
        for (int j = 0; j < 4; j++) acc[i][j] = 0ull;

    const int a_r0 = tid >> 2;          // 0..63
    const int a_c4 = tid & 3;
    const int b_r0 = tid >> 5;          // 0..7
    const int b_c4 = tid & 31;

    for (int k0 = 0; k0 < K; k0 += BK) {
#pragma unroll
        for (int i = 0; i < 2; i++) {
            int r = a_r0 + i * 64;
            int gr = bm + r;
            int gc = k0 + a_c4 * 4;
            float4 v = make_float4(0.f, 0.f, 0.f, 0.f);
            if (gr < M && gc < K)
                v = *(const float4*)(A + (size_t)gr * K + gc);
            As[a_c4 * 4 + 0][r] = v.x;
            As[a_c4 * 4 + 1][r] = v.y;
            As[a_c4 * 4 + 2][r] = v.z;
            As[a_c4 * 4 + 3][r] = v.w;
        }
#pragma unroll
        for (int i = 0; i < 2; i++) {
            int r = b_r0 + i * 8;
            int gr = k0 + r;
            float4 v = make_float4(0.f, 0.f, 0.f, 0.f);
            if (gr < K)
                v = *(const float4*)(B + (size_t)gr * N + bn + b_c4 * 4);
            *(float4*)&Bs[r][b_c4 * 4] = v;
        }
        __syncthreads();

#pragma unroll
        for (int kk = 0; kk < BK; kk++) {
            float4 a0 = *(const float4*)&As[kk][ty * 8];
            float4 a1 = *(const float4*)&As[kk][ty * 8 + 4];
            // b pairs read directly as packed 64-bit (adjacent floats)
            ulonglong2 bA = *(const ulonglong2*)&Bs[kk][tx * 8];
            ulonglong2 bB = *(const ulonglong2*)&Bs[kk][tx * 8 + 4];
            unsigned long long bp[4] = {bA.x, bA.y, bB.x, bB.y};
            float av[8] = {a0.x, a0.y, a0.z, a0.w, a1.x, a1.y, a1.z, a1.w};
#pragma unroll
            for (int i = 0; i < 8; i++) {
                unsigned long long ap = pack2(av[i], av[i]);
#pragma unroll
                for (int j = 0; j < 4; j++) fma2(acc[i][j], ap, bp[j]);
            }
        }
        __syncthreads();
    }

#pragma unroll
    for (int i = 0; i < 8; i++) {
        int r = bm + ty * 8 + i;
        if (r >= M) continue;
        float c[8];
#pragma unroll
        for (int j = 0; j < 4; j++) unpack2(acc[i][j], c[2 * j], c[2 * j + 1]);
        float* crow = C + (size_t)r * N + bn + tx * 8;
#pragma unroll
        for (int j = 0; j < 8; j += 4) {
            float4 v = make_float4(c[j], c[j + 1], c[j + 2], c[j + 3]);
            if (bias) {
                const float* bb = bias + bn + tx * 8 + j;
                v.x += bb[0]; v.y += bb[1]; v.z += bb[2]; v.w += bb[3];
            }
            if (act) {
                v.x = lrelu(v.x); v.y = lrelu(v.y);
                v.z = lrelu(v.z); v.w = lrelu(v.w);
            }
            *(float4*)(crow + j) = v;
        }
    }
}

// ---------------- fused aggregate + bias + LN + lrelu (+L2norm +pool) ----------------
// warp per node; self-loop + CSR neighbor gather, all in registers.
template <int D, bool L2NORM, bool POOL>
__global__ __launch_bounds__(256) void k_agg_ln(
    const float* __restrict__ xw, const float* __restrict__ bias,
    const float* __restrict__ gam, const float* __restrict__ bet,
    const int* __restrict__ batch, float* __restrict__ out)
{
    int row = (blockIdx.x * blockDim.x + threadIdx.x) >> 5;
    int lane = threadIdx.x & 31;
    if (row >= NN) return;
    constexpr int P4 = D / 128;  // float4s per lane (2 for 256, 1 for 128)
    const float4* xw4 = (const float4*)xw;
    float di = g_dinv[row];

    float4 acc[P4];
    {
        float s = di * di;
        size_t rb = (size_t)row * (D / 4);
#pragma unroll
        for (int j = 0; j < P4; j++) {
            float4 v = xw4[rb + lane + 32 * j];
            acc[j] = make_float4(v.x * s, v.y * s, v.z * s, v.w * s);
        }
    }
    int o0 = g_off[row];
    int dg = g_deg[row];
    for (int e = 0; e < dg; e++) {
        int s = g_csr[o0 + e];
        float nrm = g_dinv[s] * di;
        size_t sb = (size_t)s * (D / 4);
#pragma unroll
        for (int j = 0; j < P4; j++) {
            float4 v = xw4[sb + lane + 32 * j];
            acc[j].x = fmaf(v.x, nrm, acc[j].x);
            acc[j].y = fmaf(v.y, nrm, acc[j].y);
            acc[j].z = fmaf(v.z, nrm, acc[j].z);
            acc[j].w = fmaf(v.w, nrm, acc[j].w);
        }
    }

    // + bias, then LayerNorm
    const float4* bias4 = (const float4*)bias;
    float s = 0.f;
#pragma unroll
    for (int j = 0; j < P4; j++) {
        float4 bb = bias4[lane + 32 * j];
        acc[j].x += bb.x; acc[j].y += bb.y; acc[j].z += bb.z; acc[j].w += bb.w;
        s += acc[j].x + acc[j].y + acc[j].z + acc[j].w;
    }
    s = warp_sum(s);
    float mu = s * (1.0f / D);
    float q = 0.f;
#pragma unroll
    for (int j = 0; j < P4; j++) {
        float dx = acc[j].x - mu, dy = acc[j].y - mu;
        float dz = acc[j].z - mu, dw = acc[j].w - mu;
        q += dx * dx + dy * dy + dz * dz + dw * dw;
    }
    q = warp_sum(q);
    float r = rsqrtf(q * (1.0f / D) + EPSLN);

    const float4* gam4 = (const float4*)gam;
    const float4* bet4 = (const float4*)bet;
    float ss = 0.f;
#pragma unroll
    for (int j = 0; j < P4; j++) {
        float4 g = gam4[lane + 32 * j];
        float4 b = bet4[lane + 32 * j];
        float4 y;
        y.x = lrelu((acc[j].x - mu) * r * g.x + b.x);
        y.y = lrelu((acc[j].y - mu) * r * g.y + b.y);
        y.z = lrelu((acc[j].z - mu) * r * g.z + b.z);
        y.w = lrelu((acc[j].w - mu) * r * g.w + b.w);
        acc[j] = y;
        ss += y.x * y.x + y.y * y.y + y.z * y.z + y.w * y.w;
    }
    if (L2NORM) {
        ss = warp_sum(ss);
        float inv = 1.0f / fmaxf(sqrtf(ss), 1e-12f);
#pragma unroll
        for (int j = 0; j < P4; j++) {
            acc[j].x *= inv; acc[j].y *= inv; acc[j].z *= inv; acc[j].w *= inv;
        }
    }
    float4* o4 = (float4*)out + (size_t)row * (D / 4);
#pragma unroll
    for (int j = 0; j < P4; j++) o4[lane + 32 * j] = acc[j];

    if (POOL) {
        int b = batch[row];
#pragma unroll
        for (int j = 0; j < P4; j++)
            red_add_v4(g_hg + (size_t)b * DEMB + (lane + 32 * j) * 4, acc[j]);
    }
}

// ---------------- final MLP: one block (64 thr) per graph ----------------
__global__ __launch_bounds__(64) void k_mlp(
    const float* __restrict__ W1, const float* __restrict__ b1,
    const float* __restrict__ W2, const float* __restrict__ b2,
    float* __restrict__ out)
{
    int g = blockIdx.x;
    int t = threadIdx.x;  // 0..63
    __shared__ float sh[DEMB];
    __shared__ float red[2];
    sh[t] = g_hg[(size_t)g * DEMB + t];
    sh[t + 64] = g_hg[(size_t)g * DEMB + 64 + t];
    __syncthreads();
    float s = b1[t];
#pragma unroll
    for (int k = 0; k < DEMB; k++) s = fmaf(sh[k], W1[k * 64 + t], s);
    s = lrelu(s);
    s *= W2[t];  // fc2_W is [64,1]
    s = warp_sum(s);
    if ((t & 31) == 0) red[t >> 5] = s;
    __syncthreads();
    if (t == 0) out[g] = red[0] + red[1] + b2[0];
}

// ---------------- launch ----------------
extern "C" void kernel_launch(void* const* d_in, const int* in_sizes, int n_in,
                              void* d_out, int out_size)
{
    const float* x     = (const float*)d_in[0];
    const int*   ei    = (const int*)  d_in[1];
    const int*   batch = (const int*)  d_in[2];
    const float* nfcW  = (const float*)d_in[3];
    const float* nfcb  = (const float*)d_in[4];
    const float* gn1g  = (const float*)d_in[5];
    const float* gn1b  = (const float*)d_in[6];
    const float* gc1W  = (const float*)d_in[7];
    const float* gc1b  = (const float*)d_in[8];
    const float* gn2g  = (const float*)d_in[9];
    const float* gn2b  = (const float*)d_in[10];
    const float* gc2W  = (const float*)d_in[11];
    const float* gc2b  = (const float*)d_in[12];
    const float* fc1W  = (const float*)d_in[13];
    const float* fc1b  = (const float*)d_in[14];
    const float* fc2W  = (const float*)d_in[15];
    const float* fc2b  = (const float*)d_in[16];

    float* out   = (float*)d_out;         // [500]
    float* outHa = out + GGR;             // [50000*128]

    float* ha;  cudaGetSymbolAddress((void**)&ha,  g_ha);
    float* xw;  cudaGetSymbolAddress((void**)&xw,  g_xw);

    const int NB = (NN + 255) / 256;       // 196
    const int MB = (NN + BM - 1) / BM;     // 391

    // 1) degree + dinv + CSR build
    k_zero<<<(GGR * DEMB + 255) / 256, 256>>>();
    k_deg_count<<<(EE + 255) / 256, 256>>>(ei);
    k_dinv<<<NB, 256>>>();
    k_scan1<<<NB, 256>>>();
    k_scan2<<<1, 256>>>(NB);
    k_scan3<<<NB, 256>>>();
    k_fill<<<(EE + 255) / 256, 256>>>(ei);

    // 2) node feature encoder: ha = lrelu(x @ nfc_W + nfc_b)
    k_gemm<<<dim3(DH / BN, MB), 256>>>(x, nfcW, nfcb, ha, NN, FIN, DH, 1);

    // 3) GCN conv 1: xw = ha @ gc1_W; fused agg+bias+LN+lrelu -> ha
    k_gemm<<<dim3(DH / BN, MB), 256>>>(ha, gc1W, nullptr, xw, NN, DH, DH, 0);
    k_agg_ln<DH, false, false><<<(NN * 32 + 255) / 256, 256>>>(
        xw, gc1b, gn1g, gn1b, batch, ha);

    // 4) GCN conv 2: xw = ha @ gc2_W; fused agg+bias+LN+lrelu+L2norm+pool -> outHa
    k_gemm<<<dim3(DEMB / BN, MB), 256>>>(ha, gc2W, nullptr, xw, NN, DH, DEMB, 0);
    k_agg_ln<DEMB, true, true><<<(NN * 32 + 255) / 256, 256>>>(
        xw, gc2b, gn2g, gn2b, batch, outHa);

    // 5) MLP head -> out[500]
    k_mlp<<<GGR, 64>>>(fc1W, fc1b, fc2W, fc2b, out);
}

// round 7
// speedup vs baseline: 3.3233x; 1.4183x over previous
#include <cuda_runtime.h>
#include <cuda_bf16.h>
#include <math.h>
#include <stdint.h>

#define NN   50000
#define NNP  50048              // padded to multiple of 128
#define EE   400000
#define GGR  500
#define FIN  92
#define DH   256
#define DEMB 128
#define EPSLN 1e-5f

// ---------------- scratch (no allocations allowed) ----------------
__device__ float g_xw[NN * DH];            // GEMM fp32 output (pre-aggregation)
__device__ float g_dinv[NN];
__device__ int   g_deg[NN];
__device__ int   g_off[NN];
__device__ int   g_cur[NN];
__device__ int   g_csr[EE];
__device__ int   g_bsum[256];
__device__ float g_hg[GGR * DEMB];

// bf16 hi/lo split operand buffers (pad regions stay zero: zero-init, never written)
__device__ __nv_bfloat16 g_xA_hi[NNP * 128];
__device__ __nv_bfloat16 g_xA_lo[NNP * 128];
__device__ __nv_bfloat16 g_h1_hi[NNP * 256];
__device__ __nv_bfloat16 g_h1_lo[NNP * 256];
__device__ __nv_bfloat16 g_h2_hi[NNP * 256];
__device__ __nv_bfloat16 g_h2_lo[NNP * 256];
__device__ __nv_bfloat16 g_w1_hi[256 * 128], g_w1_lo[256 * 128];  // nfcW^T padded
__device__ __nv_bfloat16 g_w2_hi[256 * 256], g_w2_lo[256 * 256];  // gc1W^T
__device__ __nv_bfloat16 g_w3_hi[128 * 256], g_w3_lo[128 * 256];  // gc2W^T

// ---------------- small helpers ----------------
__device__ __forceinline__ float warp_sum(float v) {
#pragma unroll
    for (int o = 16; o > 0; o >>= 1) v += __shfl_xor_sync(0xffffffffu, v, o);
    return v;
}
__device__ __forceinline__ float lrelu(float v) { return v > 0.f ? v : 0.01f * v; }

__device__ __forceinline__ void red_add_v4(float* p, float4 v) {
    asm volatile("red.global.add.v4.f32 [%0], {%1, %2, %3, %4};"
                 :: "l"(p), "f"(v.x), "f"(v.y), "f"(v.z), "f"(v.w) : "memory");
}
__device__ __forceinline__ uint32_t pack_bf16(float a, float b) {
    __nv_bfloat162 t(__float2bfloat16(a), __float2bfloat16(b));
    return *reinterpret_cast<uint32_t*>(&t);
}
__device__ __forceinline__ uint32_t smem_u32(const void* p) {
    return (uint32_t)__cvta_generic_to_shared(p);
}
__device__ __forceinline__ void ldsm_x4(uint32_t& r0, uint32_t& r1, uint32_t& r2,
                                        uint32_t& r3, uint32_t addr) {
    asm volatile("ldmatrix.sync.aligned.m8n8.x4.shared.b16 {%0,%1,%2,%3}, [%4];"
                 : "=r"(r0), "=r"(r1), "=r"(r2), "=r"(r3) : "r"(addr));
}
__device__ __forceinline__ void mma16816(float* d, const uint32_t* a, const uint32_t* b) {
    asm volatile(
        "mma.sync.aligned.m16n8k16.row.col.f32.bf16.bf16.f32 "
        "{%0,%1,%2,%3}, {%4,%5,%6,%7}, {%8,%9}, {%0,%1,%2,%3};"
        : "+f"(d[0]), "+f"(d[1]), "+f"(d[2]), "+f"(d[3])
        : "r"(a[0]), "r"(a[1]), "r"(a[2]), "r"(a[3]), "r"(b[0]), "r"(b[1]));
}

// ---------------- degree / zero / CSR ----------------
__global__ void k_zero() {
    int i = blockIdx.x * blockDim.x + threadIdx.x;
    if (i < NN) g_deg[i] = 0;
    if (i < GGR * DEMB) g_hg[i] = 0.f;
}
__global__ void k_deg_count(const int* __restrict__ ei) {
    int e = blockIdx.x * blockDim.x + threadIdx.x;
    if (e < EE) atomicAdd(&g_deg[ei[EE + e]], 1);
}
__global__ void k_dinv() {
    int i = blockIdx.x * blockDim.x + threadIdx.x;
    if (i < NN) g_dinv[i] = rsqrtf((float)g_deg[i] + 1.0f);
}
__global__ __launch_bounds__(256) void k_scan1() {
    __shared__ int ws[8];
    int i = blockIdx.x * 256 + threadIdx.x;
    int lane = threadIdx.x & 31, w = threadIdx.x >> 5;
    int v = (i < NN) ? g_deg[i] : 0;
    int x = v;
#pragma unroll
    for (int o = 1; o < 32; o <<= 1) {
        int t = __shfl_up_sync(0xffffffffu, x, o);
        if (lane >= o) x += t;
    }
    if (lane == 31) ws[w] = x;
    __syncthreads();
    if (w == 0 && lane < 8) {
        int y = ws[lane];
#pragma unroll
        for (int o = 1; o < 8; o <<= 1) {
            int t = __shfl_up_sync(0xffu, y, o);
            if (lane >= o) y += t;
        }
        ws[lane] = y;
    }
    __syncthreads();
    int base = (w > 0) ? ws[w - 1] : 0;
    if (i < NN) g_off[i] = base + x - v;
    if (threadIdx.x == 255) g_bsum[blockIdx.x] = ws[7];
}
__global__ __launch_bounds__(256) void k_scan2(int nblk) {
    __shared__ int ws[8];
    int lane = threadIdx.x & 31, w = threadIdx.x >> 5;
    int v = (threadIdx.x < nblk) ? g_bsum[threadIdx.x] : 0;
    int x = v;
#pragma unroll
    for (int o = 1; o < 32; o <<= 1) {
        int t = __shfl_up_sync(0xffffffffu, x, o);
        if (lane >= o) x += t;
    }
    if (lane == 31) ws[w] = x;
    __syncthreads();
    if (w == 0 && lane < 8) {
        int y = ws[lane];
#pragma unroll
        for (int o = 1; o < 8; o <<= 1) {
            int t = __shfl_up_sync(0xffu, y, o);
            if (lane >= o) y += t;
        }
        ws[lane] = y;
    }
    __syncthreads();
    int base = (w > 0) ? ws[w - 1] : 0;
    if (threadIdx.x < nblk) g_bsum[threadIdx.x] = base + x - v;
}
__global__ void k_scan3() {
    int i = blockIdx.x * blockDim.x + threadIdx.x;
    if (i < NN) {
        int o = g_off[i] + g_bsum[i >> 8];
        g_off[i] = o;
        g_cur[i] = o;
    }
}
__global__ void k_fill(const int* __restrict__ ei) {
    int e = blockIdx.x * blockDim.x + threadIdx.x;
    if (e < EE) {
        int s = ei[e], d = ei[EE + e];
        int pos = atomicAdd(&g_cur[d], 1);
        g_csr[pos] = s;
    }
}

// ---------------- conversions ----------------
__global__ void k_cvt_x(const float* __restrict__ x) {
    int idx = blockIdx.x * blockDim.x + threadIdx.x;
    if (idx >= NN * 128) return;
    int row = idx >> 7, col = idx & 127;
    float v = (col < FIN) ? x[row * FIN + col] : 0.f;
    float h = __bfloat162float(__float2bfloat16(v));
    g_xA_hi[idx] = __float2bfloat16(v);
    g_xA_lo[idx] = __float2bfloat16(v - h);
}
__global__ void k_cvt_w(const float* __restrict__ W, int K, int N, int KP,
                        __nv_bfloat16* __restrict__ Oh, __nv_bfloat16* __restrict__ Ol) {
    int idx = blockIdx.x * blockDim.x + threadIdx.x;
    if (idx >= N * KP) return;
    int n = idx / KP, k = idx - n * KP;
    float v = (k < K) ? W[k * N + n] : 0.f;
    float h = __bfloat162float(__float2bfloat16(v));
    Oh[idx] = __float2bfloat16(v);
    Ol[idx] = __float2bfloat16(v - h);
}

// ---------------- mma.sync bf16x3 GEMM ----------------
// C[128 x 128] tile per CTA.  D = Ah*Bh^T + Ah*Bl^T + Al*Bh^T, fp32 accum in regs.
// A: [NNP x KP] bf16 K-major.  B: [Nrows x KP] bf16 K-major (= W^T).
// EPI 0: store fp32 C.  EPI 1: C = lrelu(C + bias), emit bf16 hi/lo.
#define SM_AH 0
#define SM_AL 16384
#define SM_BH 32768
#define SM_BL 49152
#define SMEM_BYTES 65536

template <int KP, int EPI>
__global__ __launch_bounds__(256) void k_mma(
    const __nv_bfloat16* __restrict__ Ah, const __nv_bfloat16* __restrict__ Al,
    const __nv_bfloat16* __restrict__ Bh, const __nv_bfloat16* __restrict__ Bl,
    const float* __restrict__ bias, float* __restrict__ C,
    __nv_bfloat16* __restrict__ Ohi, __nv_bfloat16* __restrict__ Olo, int Nfull)
{
    extern __shared__ __align__(128) char smem[];
    const uint32_t sb = smem_u32(smem);
    const int tid = threadIdx.x, wid = tid >> 5, lid = tid & 31;
    const int bm = blockIdx.y * 128;
    const int bn = blockIdx.x * 128;
    const int warp_m = wid & 3;   // 4 m-groups of 32 rows
    const int warp_n = wid >> 2;  // 2 n-groups of 64 cols

    float acc[2][8][4];
#pragma unroll
    for (int mt = 0; mt < 2; mt++)
#pragma unroll
        for (int nt = 0; nt < 8; nt++)
#pragma unroll
            for (int q = 0; q < 4; q++) acc[mt][nt][q] = 0.f;

    // ldmatrix lane mappings (non-trans for both A and B)
    const int a_r = (lid & 7) + ((lid >> 3) & 1) * 8;  // matrices: (r0,k0)(r8,k0)(r0,k8)(r8,k8)
    const int a_u = (lid >> 4) & 1;
    const int b_r = (lid & 7) + ((lid >> 4) & 1) * 8;  // matrices: (n0,k0)(n0,k8)(n8,k0)(n8,k8)
    const int b_u = (lid >> 3) & 1;

    constexpr int NKC = KP / 64;
    for (int kc = 0; kc < NKC; kc++) {
        // load 4 tiles of [128 rows x 64 bf16], SW128-swizzled 16B units
#pragma unroll
        for (int i = 0; i < 4; i++) {
            int idx = tid + i * 256;          // 0..1023
            int r = idx >> 3, c16 = idx & 7;
            uint32_t so = (uint32_t)(r * 128 + ((c16 ^ (r & 7)) * 16));
            size_t ga = (size_t)(bm + r) * KP + kc * 64 + c16 * 8;
            size_t gb = (size_t)(bn + r) * KP + kc * 64 + c16 * 8;
            *(uint4*)(smem + SM_AH + so) = *(const uint4*)(Ah + ga);
            *(uint4*)(smem + SM_AL + so) = *(const uint4*)(Al + ga);
            *(uint4*)(smem + SM_BH + so) = *(const uint4*)(Bh + gb);
            *(uint4*)(smem + SM_BL + so) = *(const uint4*)(Bl + gb);
        }
        __syncthreads();

#pragma unroll
        for (int k16 = 0; k16 < 4; k16++) {
            // A fragments (hi & lo) for 2 m16 tiles
            uint32_t ah[2][4], al[2][4];
#pragma unroll
            for (int mt = 0; mt < 2; mt++) {
                int row = warp_m * 32 + mt * 16 + a_r;
                int u = k16 * 2 + a_u;
                uint32_t off = (uint32_t)(row * 128 + ((u ^ (row & 7)) * 16));
                ldsm_x4(ah[mt][0], ah[mt][1], ah[mt][2], ah[mt][3], sb + SM_AH + off);
                ldsm_x4(al[mt][0], al[mt][1], al[mt][2], al[mt][3], sb + SM_AL + off);
            }
            // B fragments (hi & lo) for 8 n8 tiles (4 ldsm.x4 each = 2 tiles/ldsm)
            uint32_t bh[8][2], bl[8][2];
#pragma unroll
            for (int g = 0; g < 4; g++) {
                int row = warp_n * 64 + g * 16 + b_r;
                int u = k16 * 2 + b_u;
                uint32_t off = (uint32_t)(row * 128 + ((u ^ (row & 7)) * 16));
                ldsm_x4(bh[2 * g][0], bh[2 * g][1], bh[2 * g + 1][0], bh[2 * g + 1][1],
                        sb + SM_BH + off);
                ldsm_x4(bl[2 * g][0], bl[2 * g][1], bl[2 * g + 1][0], bl[2 * g + 1][1],
                        sb + SM_BL + off);
            }
#pragma unroll
            for (int mt = 0; mt < 2; mt++)
#pragma unroll
                for (int nt = 0; nt < 8; nt++) {
                    mma16816(acc[mt][nt], ah[mt], bh[nt]);  // Ah*Bh
                    mma16816(acc[mt][nt], ah[mt], bl[nt]);  // Ah*Bl
                    mma16816(acc[mt][nt], al[mt], bh[nt]);  // Al*Bh
                }
        }
        __syncthreads();
    }

    // epilogue straight from accumulator fragments
    const int r_base = bm + warp_m * 32 + (lid >> 2);
    const int c_base = bn + warp_n * 64 + (lid & 3) * 2;
#pragma unroll
    for (int mt = 0; mt < 2; mt++) {
#pragma unroll
        for (int h = 0; h < 2; h++) {
            int row = r_base + mt * 16 + h * 8;
            if (row >= NN) continue;
            if (EPI == 0) {
                float* cp = C + (size_t)row * Nfull;
#pragma unroll
                for (int nt = 0; nt < 8; nt++) {
                    float2 v = make_float2(acc[mt][nt][2 * h], acc[mt][nt][2 * h + 1]);
                    *(float2*)(cp + c_base + nt * 8) = v;
                }
            } else {
#pragma unroll
                for (int nt = 0; nt < 8; nt++) {
                    int col = c_base + nt * 8;
                    float v0 = lrelu(acc[mt][nt][2 * h] + bias[col]);
                    float v1 = lrelu(acc[mt][nt][2 * h + 1] + bias[col + 1]);
                    float h0 = __bfloat162float(__float2bfloat16(v0));
                    float h1 = __bfloat162float(__float2bfloat16(v1));
                    *(uint32_t*)(Ohi + (size_t)row * Nfull + col) = pack_bf16(v0, v1);
                    *(uint32_t*)(Olo + (size_t)row * Nfull + col) = pack_bf16(v0 - h0, v1 - h1);
                }
            }
        }
    }
}

// ---------------- fused aggregate + bias + LN + lrelu (+L2norm +pool / +bf16 emit) ----------------
template <int D, bool L2NORM, bool POOL, bool EMIT>
__global__ __launch_bounds__(256) void k_agg_ln(
    const float* __restrict__ xw, const float* __restrict__ bias,
    const float* __restrict__ gam, const float* __restrict__ bet,
    const int* __restrict__ batch, float* __restrict__ out,
    __nv_bfloat16* __restrict__ Ohi, __nv_bfloat16* __restrict__ Olo)
{
    int row = (blockIdx.x * blockDim.x + threadIdx.x) >> 5;
    int lane = threadIdx.x & 31;
    if (row >= NN) return;
    constexpr int P4 = D / 128;
    const float4* xw4 = (const float4*)xw;
    float di = g_dinv[row];

    float4 acc[P4];
    {
        float s = di * di;
        size_t rb = (size_t)row * (D / 4);
#pragma unroll
        for (int j = 0; j < P4; j++) {
            float4 v = xw4[rb + lane + 32 * j];
            acc[j] = make_float4(v.x * s, v.y * s, v.z * s, v.w * s);
        }
    }
    int o0 = g_off[row];
    int dg = g_deg[row];
    for (int e = 0; e < dg; e++) {
        int s = g_csr[o0 + e];
        float nrm = g_dinv[s] * di;
        size_t sbb = (size_t)s * (D / 4);
#pragma unroll
        for (int j = 0; j < P4; j++) {
            float4 v = xw4[sbb + lane + 32 * j];
            acc[j].x = fmaf(v.x, nrm, acc[j].x);
            acc[j].y = fmaf(v.y, nrm, acc[j].y);
            acc[j].z = fmaf(v.z, nrm, acc[j].z);
            acc[j].w = fmaf(v.w, nrm, acc[j].w);
        }
    }

    const float4* bias4 = (const float4*)bias;
    float s = 0.f;
#pragma unroll
    for (int j = 0; j < P4; j++) {
        float4 bb = bias4[lane + 32 * j];
        acc[j].x += bb.x; acc[j].y += bb.y; acc[j].z += bb.z; acc[j].w += bb.w;
        s += acc[j].x + acc[j].y + acc[j].z + acc[j].w;
    }
    s = warp_sum(s);
    float mu = s * (1.0f / D);
    float q = 0.f;
#pragma unroll
    for (int j = 0; j < P4; j++) {
        float dx = acc[j].x - mu, dy = acc[j].y - mu;
        float dz = acc[j].z - mu, dw = acc[j].w - mu;
        q += dx * dx + dy * dy + dz * dz + dw * dw;
    }
    q = warp_sum(q);
    float r = rsqrtf(q * (1.0f / D) + EPSLN);

    const float4* gam4 = (const float4*)gam;
    const float4* bet4 = (const float4*)bet;
    float ss = 0.f;
#pragma unroll
    for (int j = 0; j < P4; j++) {
        float4 g = gam4[lane + 32 * j];
        float4 b = bet4[lane + 32 * j];
        float4 y;
        y.x = lrelu((acc[j].x - mu) * r * g.x + b.x);
        y.y = lrelu((acc[j].y - mu) * r * g.y + b.y);
        y.z = lrelu((acc[j].z - mu) * r * g.z + b.z);
        y.w = lrelu((acc[j].w - mu) * r * g.w + b.w);
        acc[j] = y;
        ss += y.x * y.x + y.y * y.y + y.z * y.z + y.w * y.w;
    }
    if (L2NORM) {
        ss = warp_sum(ss);
        float inv = 1.0f / fmaxf(sqrtf(ss), 1e-12f);
#pragma unroll
        for (int j = 0; j < P4; j++) {
            acc[j].x *= inv; acc[j].y *= inv; acc[j].z *= inv; acc[j].w *= inv;
        }
    }
    if (EMIT) {
#pragma unroll
        for (int j = 0; j < P4; j++) {
            float4 y = acc[j];
            float hx = __bfloat162float(__float2bfloat16(y.x));
            float hy = __bfloat162float(__float2bfloat16(y.y));
            float hz = __bfloat162float(__float2bfloat16(y.z));
            float hw = __bfloat162float(__float2bfloat16(y.w));
            uint2 vh = make_uint2(pack_bf16(y.x, y.y), pack_bf16(y.z, y.w));
            uint2 vl = make_uint2(pack_bf16(y.x - hx, y.y - hy), pack_bf16(y.z - hz, y.w - hw));
            size_t o = (size_t)row * D + 4 * lane + 128 * j;
            *(uint2*)(Ohi + o) = vh;
            *(uint2*)(Olo + o) = vl;
        }
    } else {
        float4* o4 = (float4*)out + (size_t)row * (D / 4);
#pragma unroll
        for (int j = 0; j < P4; j++) o4[lane + 32 * j] = acc[j];
    }
    if (POOL) {
        int b = batch[row];
#pragma unroll
        for (int j = 0; j < P4; j++)
            red_add_v4(g_hg + (size_t)b * DEMB + (4 * lane + 128 * j), acc[j]);
    }
}

// ---------------- final MLP ----------------
__global__ __launch_bounds__(64) void k_mlp(
    const float* __restrict__ W1, const float* __restrict__ b1,
    const float* __restrict__ W2, const float* __restrict__ b2,
    float* __restrict__ out)
{
    int g = blockIdx.x;
    int t = threadIdx.x;
    __shared__ float sh[DEMB];
    __shared__ float red[2];
    sh[t] = g_hg[(size_t)g * DEMB + t];
    sh[t + 64] = g_hg[(size_t)g * DEMB + 64 + t];
    __syncthreads();
    float s = b1[t];
#pragma unroll
    for (int k = 0; k < DEMB; k++) s = fmaf(sh[k], W1[k * 64 + t], s);
    s = lrelu(s);
    s *= W2[t];
    s = warp_sum(s);
    if ((t & 31) == 0) red[t >> 5] = s;
    __syncthreads();
    if (t == 0) out[g] = red[0] + red[1] + b2[0];
}

// ---------------- launch ----------------
extern "C" void kernel_launch(void* const* d_in, const int* in_sizes, int n_in,
                              void* d_out, int out_size)
{
    const float* x     = (const float*)d_in[0];
    const int*   ei    = (const int*)  d_in[1];
    const int*   batch = (const int*)  d_in[2];
    const float* nfcW  = (const float*)d_in[3];
    const float* nfcb  = (const float*)d_in[4];
    const float* gn1g  = (const float*)d_in[5];
    const float* gn1b  = (const float*)d_in[6];
    const float* gc1W  = (const float*)d_in[7];
    const float* gc1b  = (const float*)d_in[8];
    const float* gn2g  = (const float*)d_in[9];
    const float* gn2b  = (const float*)d_in[10];
    const float* gc2W  = (const float*)d_in[11];
    const float* gc2b  = (const float*)d_in[12];
    const float* fc1W  = (const float*)d_in[13];
    const float* fc1b  = (const float*)d_in[14];
    const float* fc2W  = (const float*)d_in[15];
    const float* fc2b  = (const float*)d_in[16];

    float* out   = (float*)d_out;
    float* outHa = out + GGR;

    float* xw;  cudaGetSymbolAddress((void**)&xw, g_xw);
    __nv_bfloat16 *xAh, *xAl, *h1h, *h1l, *h2h, *h2l;
    __nv_bfloat16 *w1h, *w1l, *w2h, *w2l, *w3h, *w3l;
    cudaGetSymbolAddress((void**)&xAh, g_xA_hi); cudaGetSymbolAddress((void**)&xAl, g_xA_lo);
    cudaGetSymbolAddress((void**)&h1h, g_h1_hi); cudaGetSymbolAddress((void**)&h1l, g_h1_lo);
    cudaGetSymbolAddress((void**)&h2h, g_h2_hi); cudaGetSymbolAddress((void**)&h2l, g_h2_lo);
    cudaGetSymbolAddress((void**)&w1h, g_w1_hi); cudaGetSymbolAddress((void**)&w1l, g_w1_lo);
    cudaGetSymbolAddress((void**)&w2h, g_w2_hi); cudaGetSymbolAddress((void**)&w2l, g_w2_lo);
    cudaGetSymbolAddress((void**)&w3h, g_w3_hi); cudaGetSymbolAddress((void**)&w3l, g_w3_lo);

    cudaFuncSetAttribute(k_mma<128, 1>, cudaFuncAttributeMaxDynamicSharedMemorySize, SMEM_BYTES);
    cudaFuncSetAttribute(k_mma<256, 0>, cudaFuncAttributeMaxDynamicSharedMemorySize, SMEM_BYTES);

    const int NB = (NN + 255) / 256;
    const int MBLK = NNP / 128;  // 391

    // 1) degree + dinv + CSR build
    k_zero<<<(GGR * DEMB + 255) / 256, 256>>>();
    k_deg_count<<<(EE + 255) / 256, 256>>>(ei);
    k_dinv<<<NB, 256>>>();
    k_scan1<<<NB, 256>>>();
    k_scan2<<<1, 256>>>(NB);
    k_scan3<<<NB, 256>>>();
    k_fill<<<(EE + 255) / 256, 256>>>(ei);

    // 2) operand conversions
    k_cvt_x<<<(NN * 128 + 255) / 256, 256>>>(x);
    k_cvt_w<<<(256 * 128 + 255) / 256, 256>>>(nfcW, FIN, DH, 128, w1h, w1l);
    k_cvt_w<<<(256 * 256 + 255) / 256, 256>>>(gc1W, DH, DH, 256, w2h, w2l);
    k_cvt_w<<<(128 * 256 + 255) / 256, 256>>>(gc2W, DH, DEMB, 256, w3h, w3l);

    // 3) encoder: h1 = lrelu(x @ nfcW + b) -> bf16 hi/lo
    k_mma<128, 1><<<dim3(2, MBLK), 256, SMEM_BYTES>>>(
        xAh, xAl, w1h, w1l, nfcb, nullptr, h1h, h1l, DH);

    // 4) conv1: xw = h1 @ gc1W ; agg+LN+lrelu -> h2 bf16 hi/lo
    k_mma<256, 0><<<dim3(2, MBLK), 256, SMEM_BYTES>>>(
        h1h, h1l, w2h, w2l, nullptr, xw, nullptr, nullptr, DH);
    k_agg_ln<DH, false, false, true><<<(NN * 32 + 255) / 256, 256>>>(
        xw, gc1b, gn1g, gn1b, batch, nullptr, h2h, h2l);

    // 5) conv2: xw = h2 @ gc2W ; agg+LN+lrelu+L2norm+pool -> outHa
    k_mma<256, 0><<<dim3(1, MBLK), 256, SMEM_BYTES>>>(
        h2h, h2l, w3h, w3l, nullptr, xw, nullptr, nullptr, DEMB);
    k_agg_ln<DEMB, true, true, false><<<(NN * 32 + 255) / 256, 256>>>(
        xw, gc2b, gn2g, gn2b, batch, outHa, nullptr, nullptr);

    // 6) MLP head
    k_mlp<<<GGR, 64>>>(fc1W, fc1b, fc2W, fc2b, out);
}